// round 10
// baseline (speedup 1.0000x reference)
#include <cuda_runtime.h>
#include <cuda_bf16.h>

#define NTOK 4096
#define HEADS 8
#define DH 128
#define NKEY 256
#define TOPK 32

static __device__ __forceinline__ float neg_inf() { return __int_as_float(0xff800000); }

// order-preserving float<->uint (total order, no NaNs here)
static __device__ __forceinline__ unsigned ford(float f) {
    unsigned b = __float_as_uint(f);
    return (b & 0x80000000u) ? ~b : (b | 0x80000000u);
}
static __device__ __forceinline__ float forddec(unsigned u) {
    unsigned b = (u & 0x80000000u) ? (u & 0x7fffffffu) : ~u;
    return __uint_as_float(b);
}

// ---------------- scratch (no allocations allowed) ----------------
__device__ float g_q [(size_t)NTOK * 2048];
__device__ float g_s1[(size_t)NTOK * HEADS * 2 * TOPK];
__device__ int   g_i1[(size_t)NTOK * HEADS * 2 * TOPK];
__device__ float g_oh[(size_t)NTOK * 1024];

// =================================================================
// tf32 tensor-core GEMM: C[M,N] = A[M,K] * B[N,K]^T (+ bias[N]).
// SPLIT=1: hi/lo 3-mma (~fp32 accuracy, selection-safe).
// SPLIT=0: single-pass tf32 (rel err ~1e-4, for the final GEMM).
// Block 128x128x16, 8 warps, warp tile 32x64, m16n8k8 HMMA, 2 CTA/SM.
// =================================================================
static __device__ __forceinline__ void mma1688(float* d, const unsigned* a, const unsigned* b) {
    asm volatile(
        "mma.sync.aligned.m16n8k8.row.col.f32.tf32.tf32.f32 "
        "{%0,%1,%2,%3}, {%4,%5,%6,%7}, {%8,%9}, {%0,%1,%2,%3};"
        : "+f"(d[0]), "+f"(d[1]), "+f"(d[2]), "+f"(d[3])
        : "r"(a[0]), "r"(a[1]), "r"(a[2]), "r"(a[3]), "r"(b[0]), "r"(b[1]));
}
static __device__ __forceinline__ unsigned f2tf32(float f) {
    unsigned r; asm("cvt.rna.tf32.f32 %0, %1;" : "=r"(r) : "f"(f)); return r;
}
static __device__ __forceinline__ void split_tf32(float f, unsigned& hi, unsigned& lo) {
    hi = f2tf32(f);                                     // round-to-nearest tf32
    lo = f2tf32(f - __uint_as_float(hi));               // exact residual, rounded
}

template <int SPLIT>
__global__ __launch_bounds__(256, 2)
void mma_tn(const float* __restrict__ A, const float* __restrict__ B,
            float* __restrict__ C, const float* __restrict__ bias,
            int M, int N, int K, int lda, int ldb, int ldc)
{
    __shared__ float As[128][20];   // [m][k]
    __shared__ float Bs[128][20];   // [n][k]

    const int tid  = threadIdx.x;
    const int lane = tid & 31;
    const int wid  = tid >> 5;
    const int wm   = wid & 3;
    const int wn   = wid >> 2;
    const int m0   = blockIdx.y * 128;
    const int n0   = blockIdx.x * 128;

    const int r0 = tid >> 2;
    const int r1 = r0 + 64;
    const int kc = (tid & 3) << 2;

    const float* Ap0 = A + (size_t)(m0 + r0) * lda + kc;
    const float* Ap1 = A + (size_t)(m0 + r1) * lda + kc;
    const float* Bp0 = B + (size_t)(n0 + r0) * ldb + kc;
    const float* Bp1 = B + (size_t)(n0 + r1) * ldb + kc;

    float4 ra0 = *(const float4*)Ap0;
    float4 ra1 = *(const float4*)Ap1;
    float4 rb0 = *(const float4*)Bp0;
    float4 rb1 = *(const float4*)Bp1;

    float d[2][8][4];
    #pragma unroll
    for (int mt = 0; mt < 2; mt++)
        #pragma unroll
        for (int nt = 0; nt < 8; nt++)
            #pragma unroll
            for (int i = 0; i < 4; i++) d[mt][nt][i] = 0.f;

    const int frow = lane >> 2;
    const int fcol = lane & 3;
    const int nsteps = K >> 4;

    for (int s = 0; s < nsteps; s++) {
        __syncthreads();
        *(float4*)&As[r0][kc] = ra0;
        *(float4*)&As[r1][kc] = ra1;
        *(float4*)&Bs[r0][kc] = rb0;
        *(float4*)&Bs[r1][kc] = rb1;
        __syncthreads();
        if (s + 1 < nsteps) {           // overlaps the whole compute below
            ra0 = *(const float4*)(Ap0 + (s+1)*16);
            ra1 = *(const float4*)(Ap1 + (s+1)*16);
            rb0 = *(const float4*)(Bp0 + (s+1)*16);
            rb1 = *(const float4*)(Bp1 + (s+1)*16);
        }
        #pragma unroll
        for (int k0 = 0; k0 < 16; k0 += 8) {
            unsigned ah[2][4], al[2][4];
            #pragma unroll
            for (int mt = 0; mt < 2; mt++) {
                const int mb = wm*32 + mt*16;
                if (SPLIT) {
                    split_tf32(As[mb + frow    ][k0 + fcol    ], ah[mt][0], al[mt][0]);
                    split_tf32(As[mb + frow + 8][k0 + fcol    ], ah[mt][1], al[mt][1]);
                    split_tf32(As[mb + frow    ][k0 + fcol + 4], ah[mt][2], al[mt][2]);
                    split_tf32(As[mb + frow + 8][k0 + fcol + 4], ah[mt][3], al[mt][3]);
                } else {
                    ah[mt][0] = f2tf32(As[mb + frow    ][k0 + fcol    ]);
                    ah[mt][1] = f2tf32(As[mb + frow + 8][k0 + fcol    ]);
                    ah[mt][2] = f2tf32(As[mb + frow    ][k0 + fcol + 4]);
                    ah[mt][3] = f2tf32(As[mb + frow + 8][k0 + fcol + 4]);
                }
            }
            #pragma unroll
            for (int nt = 0; nt < 8; nt++) {
                const int n = wn*64 + nt*8 + frow;
                unsigned bh[2], bl[2];
                if (SPLIT) {
                    split_tf32(Bs[n][k0 + fcol    ], bh[0], bl[0]);
                    split_tf32(Bs[n][k0 + fcol + 4], bh[1], bl[1]);
                    mma1688(d[0][nt], ah[0], bh);
                    mma1688(d[0][nt], ah[0], bl);
                    mma1688(d[0][nt], al[0], bh);
                    mma1688(d[1][nt], ah[1], bh);
                    mma1688(d[1][nt], ah[1], bl);
                    mma1688(d[1][nt], al[1], bh);
                } else {
                    bh[0] = f2tf32(Bs[n][k0 + fcol    ]);
                    bh[1] = f2tf32(Bs[n][k0 + fcol + 4]);
                    mma1688(d[0][nt], ah[0], bh);
                    mma1688(d[1][nt], ah[1], bh);
                }
            }
        }
    }

    #pragma unroll
    for (int mt = 0; mt < 2; mt++) {
        const int row = m0 + wm*32 + mt*16 + frow;
        #pragma unroll
        for (int nt = 0; nt < 8; nt++) {
            const int col = n0 + wn*64 + nt*8 + fcol*2;
            float2 bv = make_float2(0.f, 0.f);
            if (bias) bv = *(const float2*)(bias + col);
            float2 o0 = make_float2(d[mt][nt][0] + bv.x, d[mt][nt][1] + bv.y);
            float2 o1 = make_float2(d[mt][nt][2] + bv.x, d[mt][nt][3] + bv.y);
            *(float2*)&C[(size_t)row * ldc + col]       = o0;
            *(float2*)&C[(size_t)(row + 8) * ldc + col] = o1;
        }
    }
}

// =================================================================
// Kernel 2: dots (one (h,p), 32-token tile vs 256 keys) + top-32
// (desc, ties -> smaller index).  Extraction runs two independent
// token chains interleaved to hide REDUX latency.
// =================================================================
__global__ __launch_bounds__(256)
void dots_topk_kernel(const float* __restrict__ qm, const float* __restrict__ keys)
{
    __shared__ float As[8][36];
    __shared__ float Bs[8][264];
    __shared__ float dsm[32*256];

    const int tid  = threadIdx.x;
    const int hp   = blockIdx.y;
    const int h    = hp >> 1;
    const int p    = hp & 1;
    const int t0g  = blockIdx.x * 32;

    const int ty   = tid >> 5;
    const int lane = tid & 31;

    const int at = tid >> 1;
    const int ak = (tid & 1) << 2;
    const float* Ap = qm + (size_t)(t0g + at) * 2048 + p*1024 + h*DH + ak;

    const int bn0 = tid >> 1;
    const int bn1 = bn0 + 128;
    const int bk  = (tid & 1) << 2;
    const float* Kb  = keys + (size_t)h * (NKEY*2*DH) + (size_t)p * DH;
    const float* Bp0 = Kb + (size_t)bn0 * (2*DH) + bk;
    const float* Bp1 = Kb + (size_t)bn1 * (2*DH) + bk;

    float4 ra = make_float4(0.f,0.f,0.f,0.f);
    if (tid < 64) ra = *(const float4*)Ap;
    float4 rb0 = *(const float4*)Bp0;
    float4 rb1 = *(const float4*)Bp1;

    float acc[4][8];
    #pragma unroll
    for (int r = 0; r < 4; r++)
        #pragma unroll
        for (int c = 0; c < 8; c++) acc[r][c] = 0.f;

    for (int s = 0; s < 16; s++) {
        __syncthreads();
        if (tid < 64) {
            As[ak+0][at] = ra.x; As[ak+1][at] = ra.y;
            As[ak+2][at] = ra.z; As[ak+3][at] = ra.w;
        }
        Bs[bk+0][bn0] = rb0.x; Bs[bk+1][bn0] = rb0.y;
        Bs[bk+2][bn0] = rb0.z; Bs[bk+3][bn0] = rb0.w;
        Bs[bk+0][bn1] = rb1.x; Bs[bk+1][bn1] = rb1.y;
        Bs[bk+2][bn1] = rb1.z; Bs[bk+3][bn1] = rb1.w;
        __syncthreads();
        if (s + 1 < 16) {
            if (tid < 64) ra = *(const float4*)(Ap + (s+1)*8);
            rb0 = *(const float4*)(Bp0 + (s+1)*8);
            rb1 = *(const float4*)(Bp1 + (s+1)*8);
        }
        #pragma unroll
        for (int kk = 0; kk < 8; kk++) {
            float4 a4 = *(const float4*)&As[kk][ty*4];
            float4 b0 = *(const float4*)&Bs[kk][lane*4];
            float4 b1 = *(const float4*)&Bs[kk][128 + lane*4];
            float ar[4] = {a4.x,a4.y,a4.z,a4.w};
            float bc[8] = {b0.x,b0.y,b0.z,b0.w,b1.x,b1.y,b1.z,b1.w};
            #pragma unroll
            for (int r = 0; r < 4; r++)
                #pragma unroll
                for (int c = 0; c < 8; c++)
                    acc[r][c] = fmaf(ar[r], bc[c], acc[r][c]);
        }
    }

    #pragma unroll
    for (int r = 0; r < 4; r++) {
        *(float4*)&dsm[(ty*4+r)*256 + lane*4]       = make_float4(acc[r][0],acc[r][1],acc[r][2],acc[r][3]);
        *(float4*)&dsm[(ty*4+r)*256 + 128 + lane*4] = make_float4(acc[r][4],acc[r][5],acc[r][6],acc[r][7]);
    }
    __syncthreads();

    #pragma unroll 1
    for (int it2 = 0; it2 < 2; it2++) {       // two interleaved chains per pass
        const int tA = ty*4 + it2*2;
        const int tB = tA + 1;
        float vA[8], vB[8];
        #pragma unroll
        for (int j = 0; j < 8; j++) {
            vA[j] = dsm[tA*256 + j*32 + lane];
            vB[j] = dsm[tB*256 + j*32 + lane];
        }
        unsigned takenA = 0u, takenB = 0u;
        float outvA = 0.f, outvB = 0.f; int outnA = 0, outnB = 0;
        #pragma unroll 1
        for (int kk = 0; kk < 32; kk++) {
            float lvA = neg_inf(); int lnA = 0x7fffffff;
            float lvB = neg_inf(); int lnB = 0x7fffffff;
            #pragma unroll
            for (int j = 0; j < 8; j++) {
                float cA = ((takenA >> j) & 1u) ? neg_inf() : vA[j];
                if (cA > lvA) { lvA = cA; lnA = j*32 + lane; }
                float cB = ((takenB >> j) & 1u) ? neg_inf() : vB[j];
                if (cB > lvB) { lvB = cB; lnB = j*32 + lane; }
            }
            const unsigned uA    = ford(lvA);
            const unsigned uB    = ford(lvB);
            const unsigned umaxA = __reduce_max_sync(0xffffffffu, uA);
            const unsigned umaxB = __reduce_max_sync(0xffffffffu, uB);
            const unsigned clnA  = (uA == umaxA) ? (unsigned)lnA : 0xffffffffu;
            const unsigned clnB  = (uB == umaxB) ? (unsigned)lnB : 0xffffffffu;
            const unsigned wlnA  = __reduce_min_sync(0xffffffffu, clnA);
            const unsigned wlnB  = __reduce_min_sync(0xffffffffu, clnB);
            if (kk == lane) { outvA = forddec(umaxA); outnA = (int)wlnA;
                              outvB = forddec(umaxB); outnB = (int)wlnB; }
            if ((wlnA & 31u) == (unsigned)lane) takenA |= 1u << (wlnA >> 5);
            if ((wlnB & 31u) == (unsigned)lane) takenB |= 1u << (wlnB >> 5);
        }
        const size_t baseA = ((((size_t)(t0g + tA)) * HEADS + h) * 2 + p) * TOPK;
        const size_t baseB = ((((size_t)(t0g + tB)) * HEADS + h) * 2 + p) * TOPK;
        g_s1[baseA + lane] = outvA;
        g_i1[baseA + lane] = outnA;
        g_s1[baseB + lane] = outvB;
        g_i1[baseB + lane] = outnB;
    }
}

// =================================================================
// Kernel 3: combine (sorted-column pointer merge), softmax,
// 32-row value gather, weighted sum.
// =================================================================
__global__ __launch_bounds__(256)
void combine_kernel(const float* __restrict__ values)
{
    const int warp = threadIdx.x >> 5;
    const int lane = threadIdx.x & 31;
    const int slot = blockIdx.x * 8 + warp;
    const int t = slot & 2047;
    const int h = (slot >> 11) & 7;
    const int b = slot >> 14;
    const int u = t >> 1;
    const int p = t & 1;

    const size_t base0 = ((((size_t)(b*2048 + u))        * HEADS + h) * 2 + p) * TOPK;
    const size_t base1 = ((((size_t)(b*2048 + u + 1024)) * HEADS + h) * 2 + p) * TOPK;
    const float s0 = g_s1[base0 + lane];
    const int   i0 = g_i1[base0 + lane];
    const float s1 = g_s1[base1 + lane];
    const int   i1 = g_i1[base1 + lane];

    int ptr = 0;
    float rv = 0.f; int rflat = 0;
    #pragma unroll 1
    for (int it = 0; it < 32; it++) {
        const int pp = ptr < 32 ? ptr : 31;
        float cv = __shfl_sync(0xffffffffu, s0, pp) + s1;
        int fl = ptr * 32 + lane;
        if (ptr >= 32) { cv = neg_inf(); fl = 0x7fffffff; }
        const unsigned uu   = ford(cv);
        const unsigned umax = __reduce_max_sync(0xffffffffu, uu);
        const unsigned cfl  = (uu == umax) ? (unsigned)fl : 0xffffffffu;
        const unsigned wfl  = __reduce_min_sync(0xffffffffu, cfl);
        if (it == lane) { rv = forddec(umax); rflat = (int)wfl; }
        if ((wfl & 31u) == (unsigned)lane && wfl != 0xffffffffu) ptr++;
    }

    const float mx = __shfl_sync(0xffffffffu, rv, 0);
    float e = __expf(rv - mx);
    float ssum = e;
    #pragma unroll
    for (int o = 16; o > 0; o >>= 1) ssum += __shfl_xor_sync(0xffffffffu, ssum, o);
    const float w = e / ssum;

    const int si = rflat >> 5;
    const int sj = rflat & 31;
    const int iv0 = __shfl_sync(0xffffffffu, i0, si);
    const int iv1 = __shfl_sync(0xffffffffu, i1, sj);
    const int vi = iv0 * NKEY + iv1;

    const float* vb = values + (size_t)h * ((size_t)NKEY*NKEY) * DH;
    float4 acc = make_float4(0.f,0.f,0.f,0.f);
    #pragma unroll 4
    for (int k = 0; k < 32; k++) {
        const int   vik = __shfl_sync(0xffffffffu, vi, k);
        const float wk  = __shfl_sync(0xffffffffu, w,  k);
        const float4 row = *(const float4*)(vb + (size_t)vik * DH + lane*4);
        acc.x = fmaf(wk, row.x, acc.x);
        acc.y = fmaf(wk, row.y, acc.y);
        acc.z = fmaf(wk, row.z, acc.z);
        acc.w = fmaf(wk, row.w, acc.w);
    }
    *(float4*)&g_oh[(size_t)(b*2048 + t) * 1024 + h*DH + lane*4] = acc;
}

// =================================================================
extern "C" void kernel_launch(void* const* d_in, const int* in_sizes, int n_in,
                              void* d_out, int out_size)
{
    const float* x      = (const float*)d_in[0];
    const float* Wq     = (const float*)d_in[1];
    const float* keys   = (const float*)d_in[2];
    const float* values = (const float*)d_in[3];
    const float* Wo     = (const float*)d_in[4];
    const float* bo     = (const float*)d_in[5];
    float* out = (float*)d_out;

    float* q;  cudaGetSymbolAddress((void**)&q,  g_q);
    float* oh; cudaGetSymbolAddress((void**)&oh, g_oh);

    // 1) q = x @ Wq^T (feeds top-k selection -> split precision)
    mma_tn<1><<<dim3(2048/128, 4096/128), 256>>>(x, Wq, q, nullptr,
                                                 4096, 2048, 1024, 1024, 1024, 2048);
    // 2) dots + stage-1 top-32
    dots_topk_kernel<<<dim3(4096/32, 16), 256>>>(q, keys);
    // 3) combine + softmax + gather
    combine_kernel<<<4096, 256>>>(values);
    // 4) out = oh @ Wo^T + bo (tolerance-checked output -> single-pass tf32)
    mma_tn<0><<<dim3(1024/128, 4096/128), 256>>>(oh, Wo, out, bo,
                                                 4096, 1024, 1024, 1024, 1024, 1024);
}

// round 14
// speedup vs baseline: 1.0552x; 1.0552x over previous
#include <cuda_runtime.h>
#include <cuda_bf16.h>

#define NTOK 4096
#define HEADS 8
#define DH 128
#define NKEY 256
#define TOPK 32

static __device__ __forceinline__ float neg_inf() { return __int_as_float(0xff800000); }

// order-preserving float<->uint (total order, no NaNs here)
static __device__ __forceinline__ unsigned ford(float f) {
    unsigned b = __float_as_uint(f);
    return (b & 0x80000000u) ? ~b : (b | 0x80000000u);
}
static __device__ __forceinline__ float forddec(unsigned u) {
    unsigned b = (u & 0x80000000u) ? (u & 0x7fffffffu) : ~u;
    return __uint_as_float(b);
}

// ---------------- scratch (no allocations allowed) ----------------
__device__ float g_q [(size_t)NTOK * 2048];
__device__ float g_s1[(size_t)NTOK * HEADS * 2 * TOPK];
__device__ int   g_i1[(size_t)NTOK * HEADS * 2 * TOPK];
__device__ float g_oh[(size_t)NTOK * 1024];

// =================================================================
// tf32 tensor-core GEMM: C[M,N] = A[M,K] * B[N,K]^T (+ bias[N]).
// SPLIT=1: hi/lo 3-mma (~fp32 accuracy, selection-safe), 1 CTA/SM
//          (needs ~146 regs; capping to 2 CTAs caused spills in R10).
// SPLIT=0: single-pass tf32 (~1e-4), 2 CTA/SM (123 regs, measured).
// =================================================================
static __device__ __forceinline__ void mma1688(float* d, const unsigned* a, const unsigned* b) {
    asm volatile(
        "mma.sync.aligned.m16n8k8.row.col.f32.tf32.tf32.f32 "
        "{%0,%1,%2,%3}, {%4,%5,%6,%7}, {%8,%9}, {%0,%1,%2,%3};"
        : "+f"(d[0]), "+f"(d[1]), "+f"(d[2]), "+f"(d[3])
        : "r"(a[0]), "r"(a[1]), "r"(a[2]), "r"(a[3]), "r"(b[0]), "r"(b[1]));
}
static __device__ __forceinline__ unsigned f2tf32(float f) {
    unsigned r; asm("cvt.rna.tf32.f32 %0, %1;" : "=r"(r) : "f"(f)); return r;
}
static __device__ __forceinline__ void split_tf32(float f, unsigned& hi, unsigned& lo) {
    hi = f2tf32(f);
    lo = f2tf32(f - __uint_as_float(hi));
}

template <int SPLIT, int MINB>
__global__ __launch_bounds__(256, MINB)
void mma_tn(const float* __restrict__ A, const float* __restrict__ B,
            float* __restrict__ C, const float* __restrict__ bias,
            int M, int N, int K, int lda, int ldb, int ldc)
{
    __shared__ float As[128][20];
    __shared__ float Bs[128][20];

    const int tid  = threadIdx.x;
    const int lane = tid & 31;
    const int wid  = tid >> 5;
    const int wm   = wid & 3;
    const int wn   = wid >> 2;
    const int m0   = blockIdx.y * 128;
    const int n0   = blockIdx.x * 128;

    const int r0 = tid >> 2;
    const int r1 = r0 + 64;
    const int kc = (tid & 3) << 2;

    const float* Ap0 = A + (size_t)(m0 + r0) * lda + kc;
    const float* Ap1 = A + (size_t)(m0 + r1) * lda + kc;
    const float* Bp0 = B + (size_t)(n0 + r0) * ldb + kc;
    const float* Bp1 = B + (size_t)(n0 + r1) * ldb + kc;

    float4 ra0 = *(const float4*)Ap0;
    float4 ra1 = *(const float4*)Ap1;
    float4 rb0 = *(const float4*)Bp0;
    float4 rb1 = *(const float4*)Bp1;

    float d[2][8][4];
    #pragma unroll
    for (int mt = 0; mt < 2; mt++)
        #pragma unroll
        for (int nt = 0; nt < 8; nt++)
            #pragma unroll
            for (int i = 0; i < 4; i++) d[mt][nt][i] = 0.f;

    const int frow = lane >> 2;
    const int fcol = lane & 3;
    const int nsteps = K >> 4;

    for (int s = 0; s < nsteps; s++) {
        __syncthreads();
        *(float4*)&As[r0][kc] = ra0;
        *(float4*)&As[r1][kc] = ra1;
        *(float4*)&Bs[r0][kc] = rb0;
        *(float4*)&Bs[r1][kc] = rb1;
        __syncthreads();
        if (s + 1 < nsteps) {
            ra0 = *(const float4*)(Ap0 + (s+1)*16);
            ra1 = *(const float4*)(Ap1 + (s+1)*16);
            rb0 = *(const float4*)(Bp0 + (s+1)*16);
            rb1 = *(const float4*)(Bp1 + (s+1)*16);
        }
        #pragma unroll
        for (int k0 = 0; k0 < 16; k0 += 8) {
            unsigned ah[2][4], al[2][4];
            #pragma unroll
            for (int mt = 0; mt < 2; mt++) {
                const int mb = wm*32 + mt*16;
                if (SPLIT) {
                    split_tf32(As[mb + frow    ][k0 + fcol    ], ah[mt][0], al[mt][0]);
                    split_tf32(As[mb + frow + 8][k0 + fcol    ], ah[mt][1], al[mt][1]);
                    split_tf32(As[mb + frow    ][k0 + fcol + 4], ah[mt][2], al[mt][2]);
                    split_tf32(As[mb + frow + 8][k0 + fcol + 4], ah[mt][3], al[mt][3]);
                } else {
                    ah[mt][0] = f2tf32(As[mb + frow    ][k0 + fcol    ]);
                    ah[mt][1] = f2tf32(As[mb + frow + 8][k0 + fcol    ]);
                    ah[mt][2] = f2tf32(As[mb + frow    ][k0 + fcol + 4]);
                    ah[mt][3] = f2tf32(As[mb + frow + 8][k0 + fcol + 4]);
                }
            }
            #pragma unroll
            for (int nt = 0; nt < 8; nt++) {
                const int n = wn*64 + nt*8 + frow;
                unsigned bh[2], bl[2];
                if (SPLIT) {
                    split_tf32(Bs[n][k0 + fcol    ], bh[0], bl[0]);
                    split_tf32(Bs[n][k0 + fcol + 4], bh[1], bl[1]);
                    mma1688(d[0][nt], ah[0], bh);
                    mma1688(d[0][nt], ah[0], bl);
                    mma1688(d[0][nt], al[0], bh);
                    mma1688(d[1][nt], ah[1], bh);
                    mma1688(d[1][nt], ah[1], bl);
                    mma1688(d[1][nt], al[1], bh);
                } else {
                    bh[0] = f2tf32(Bs[n][k0 + fcol    ]);
                    bh[1] = f2tf32(Bs[n][k0 + fcol + 4]);
                    mma1688(d[0][nt], ah[0], bh);
                    mma1688(d[1][nt], ah[1], bh);
                }
            }
        }
    }

    #pragma unroll
    for (int mt = 0; mt < 2; mt++) {
        const int row = m0 + wm*32 + mt*16 + frow;
        #pragma unroll
        for (int nt = 0; nt < 8; nt++) {
            const int col = n0 + wn*64 + nt*8 + fcol*2;
            float2 bv = make_float2(0.f, 0.f);
            if (bias) bv = *(const float2*)(bias + col);
            float2 o0 = make_float2(d[mt][nt][0] + bv.x, d[mt][nt][1] + bv.y);
            float2 o1 = make_float2(d[mt][nt][2] + bv.x, d[mt][nt][3] + bv.y);
            *(float2*)&C[(size_t)row * ldc + col]       = o0;
            *(float2*)&C[(size_t)(row + 8) * ldc + col] = o1;
        }
    }
}

// =================================================================
// Kernel 2: dots (one (h,p), 32-token tile vs 256 keys) + top-32.
// Extraction: 4 interleaved chains/warp, 1 REDUX + ballot per round
// (tie-break = lowest lane; exact ties are measure-zero).
// =================================================================
__global__ __launch_bounds__(256)
void dots_topk_kernel(const float* __restrict__ qm, const float* __restrict__ keys)
{
    __shared__ float As[8][36];
    __shared__ float Bs[8][264];
    __shared__ float dsm[32*256];

    const int tid  = threadIdx.x;
    const int hp   = blockIdx.y;
    const int h    = hp >> 1;
    const int p    = hp & 1;
    const int t0g  = blockIdx.x * 32;

    const int ty   = tid >> 5;
    const int lane = tid & 31;

    const int at = tid >> 1;
    const int ak = (tid & 1) << 2;
    const float* Ap = qm + (size_t)(t0g + at) * 2048 + p*1024 + h*DH + ak;

    const int bn0 = tid >> 1;
    const int bn1 = bn0 + 128;
    const int bk  = (tid & 1) << 2;
    const float* Kb  = keys + (size_t)h * (NKEY*2*DH) + (size_t)p * DH;
    const float* Bp0 = Kb + (size_t)bn0 * (2*DH) + bk;
    const float* Bp1 = Kb + (size_t)bn1 * (2*DH) + bk;

    float4 ra = make_float4(0.f,0.f,0.f,0.f);
    if (tid < 64) ra = *(const float4*)Ap;
    float4 rb0 = *(const float4*)Bp0;
    float4 rb1 = *(const float4*)Bp1;

    float acc[4][8];
    #pragma unroll
    for (int r = 0; r < 4; r++)
        #pragma unroll
        for (int c = 0; c < 8; c++) acc[r][c] = 0.f;

    for (int s = 0; s < 16; s++) {
        __syncthreads();
        if (tid < 64) {
            As[ak+0][at] = ra.x; As[ak+1][at] = ra.y;
            As[ak+2][at] = ra.z; As[ak+3][at] = ra.w;
        }
        Bs[bk+0][bn0] = rb0.x; Bs[bk+1][bn0] = rb0.y;
        Bs[bk+2][bn0] = rb0.z; Bs[bk+3][bn0] = rb0.w;
        Bs[bk+0][bn1] = rb1.x; Bs[bk+1][bn1] = rb1.y;
        Bs[bk+2][bn1] = rb1.z; Bs[bk+3][bn1] = rb1.w;
        __syncthreads();
        if (s + 1 < 16) {
            if (tid < 64) ra = *(const float4*)(Ap + (s+1)*8);
            rb0 = *(const float4*)(Bp0 + (s+1)*8);
            rb1 = *(const float4*)(Bp1 + (s+1)*8);
        }
        #pragma unroll
        for (int kk = 0; kk < 8; kk++) {
            float4 a4 = *(const float4*)&As[kk][ty*4];
            float4 b0 = *(const float4*)&Bs[kk][lane*4];
            float4 b1 = *(const float4*)&Bs[kk][128 + lane*4];
            float ar[4] = {a4.x,a4.y,a4.z,a4.w};
            float bc[8] = {b0.x,b0.y,b0.z,b0.w,b1.x,b1.y,b1.z,b1.w};
            #pragma unroll
            for (int r = 0; r < 4; r++)
                #pragma unroll
                for (int c = 0; c < 8; c++)
                    acc[r][c] = fmaf(ar[r], bc[c], acc[r][c]);
        }
    }

    #pragma unroll
    for (int r = 0; r < 4; r++) {
        *(float4*)&dsm[(ty*4+r)*256 + lane*4]       = make_float4(acc[r][0],acc[r][1],acc[r][2],acc[r][3]);
        *(float4*)&dsm[(ty*4+r)*256 + 128 + lane*4] = make_float4(acc[r][4],acc[r][5],acc[r][6],acc[r][7]);
    }
    __syncthreads();

    // 4 interleaved extraction chains (one per token of this warp)
    float v[4][8];
    #pragma unroll
    for (int c = 0; c < 4; c++)
        #pragma unroll
        for (int j = 0; j < 8; j++)
            v[c][j] = dsm[(ty*4+c)*256 + j*32 + lane];

    unsigned taken[4] = {0u,0u,0u,0u};
    float outv[4] = {0.f,0.f,0.f,0.f};
    int   outn[4] = {0,0,0,0};

    #pragma unroll 1
    for (int kk = 0; kk < 32; kk++) {
        unsigned u[4]; int ln[4];
        #pragma unroll
        for (int c = 0; c < 4; c++) {
            float lv = neg_inf(); int l = 0x7fffffff;
            #pragma unroll
            for (int j = 0; j < 8; j++) {
                float cand = ((taken[c] >> j) & 1u) ? neg_inf() : v[c][j];
                if (cand > lv) { lv = cand; l = j*32 + lane; }
            }
            u[c] = ford(lv); ln[c] = l;
        }
        unsigned umax[4];
        #pragma unroll
        for (int c = 0; c < 4; c++) umax[c] = __reduce_max_sync(0xffffffffu, u[c]);
        unsigned ball[4];
        #pragma unroll
        for (int c = 0; c < 4; c++) ball[c] = __ballot_sync(0xffffffffu, u[c] == umax[c]);
        #pragma unroll
        for (int c = 0; c < 4; c++) {
            const int wl = __ffs(ball[c]) - 1;
            const int wn = __shfl_sync(0xffffffffu, ln[c], wl);
            if (kk == lane) { outv[c] = forddec(umax[c]); outn[c] = wn; }
            if (wl == lane) taken[c] |= 1u << (ln[c] >> 5);
        }
    }

    #pragma unroll
    for (int c = 0; c < 4; c++) {
        const size_t base = ((((size_t)(t0g + ty*4 + c)) * HEADS + h) * 2 + p) * TOPK;
        g_s1[base + lane] = outv[c];
        g_i1[base + lane] = outn[c];
    }
}

// =================================================================
// Kernel 3: combine, 2 slots per warp (p=0 and p=1 of same (b,h,u)),
// interleaved merge rounds + interleaved gather for MLP.
// =================================================================
__global__ __launch_bounds__(256)
void combine_kernel(const float* __restrict__ values)
{
    const int warp  = threadIdx.x >> 5;
    const int lane  = threadIdx.x & 31;
    const int slotA = blockIdx.x * 16 + warp * 2;   // even slot: p=0
    const int t  = slotA & 2047;                    // even
    const int h  = (slotA >> 11) & 7;
    const int b  = slotA >> 14;
    const int u  = t >> 1;

    const size_t b0A = ((((size_t)(b*2048 + u))        * HEADS + h) * 2 + 0) * TOPK;
    const size_t b1A = ((((size_t)(b*2048 + u + 1024)) * HEADS + h) * 2 + 0) * TOPK;
    const size_t b0B = b0A + TOPK;  // p=1
    const size_t b1B = b1A + TOPK;

    const float s0A = g_s1[b0A + lane]; const int i0A = g_i1[b0A + lane];
    const float s1A = g_s1[b1A + lane]; const int i1A = g_i1[b1A + lane];
    const float s0B = g_s1[b0B + lane]; const int i0B = g_i1[b0B + lane];
    const float s1B = g_s1[b1B + lane]; const int i1B = g_i1[b1B + lane];

    int ptrA = 0, ptrB = 0;
    float rvA = 0.f, rvB = 0.f; int rfA = 0, rfB = 0;
    #pragma unroll 1
    for (int it = 0; it < 32; it++) {
        const int ppA = ptrA < 32 ? ptrA : 31;
        const int ppB = ptrB < 32 ? ptrB : 31;
        float cvA = __shfl_sync(0xffffffffu, s0A, ppA) + s1A;
        float cvB = __shfl_sync(0xffffffffu, s0B, ppB) + s1B;
        int flA = ptrA * 32 + lane;
        int flB = ptrB * 32 + lane;
        if (ptrA >= 32) { cvA = neg_inf(); flA = 0x7fffffff; }
        if (ptrB >= 32) { cvB = neg_inf(); flB = 0x7fffffff; }
        const unsigned uA = ford(cvA), uB = ford(cvB);
        const unsigned umA = __reduce_max_sync(0xffffffffu, uA);
        const unsigned umB = __reduce_max_sync(0xffffffffu, uB);
        const unsigned baA = __ballot_sync(0xffffffffu, uA == umA);
        const unsigned baB = __ballot_sync(0xffffffffu, uB == umB);
        const int wlA = __ffs(baA) - 1;
        const int wlB = __ffs(baB) - 1;
        const int wfA = __shfl_sync(0xffffffffu, flA, wlA);
        const int wfB = __shfl_sync(0xffffffffu, flB, wlB);
        if (it == lane) { rvA = forddec(umA); rfA = wfA;
                          rvB = forddec(umB); rfB = wfB; }
        if (wlA == lane && flA != 0x7fffffff) ptrA++;
        if (wlB == lane && flB != 0x7fffffff) ptrB++;
    }

    // softmax (lane 0 holds max: extraction is descending)
    const float mxA = __shfl_sync(0xffffffffu, rvA, 0);
    const float mxB = __shfl_sync(0xffffffffu, rvB, 0);
    float eA = __expf(rvA - mxA);
    float eB = __expf(rvB - mxB);
    float sA = eA, sB = eB;
    #pragma unroll
    for (int o = 16; o > 0; o >>= 1) {
        sA += __shfl_xor_sync(0xffffffffu, sA, o);
        sB += __shfl_xor_sync(0xffffffffu, sB, o);
    }
    const float wA = eA / sA;
    const float wB = eB / sB;

    const int viA = __shfl_sync(0xffffffffu, i0A, rfA >> 5) * NKEY
                  + __shfl_sync(0xffffffffu, i1A, rfA & 31);
    const int viB = __shfl_sync(0xffffffffu, i0B, rfB >> 5) * NKEY
                  + __shfl_sync(0xffffffffu, i1B, rfB & 31);

    const float* vb = values + (size_t)h * ((size_t)NKEY*NKEY) * DH;
    float4 accA = make_float4(0.f,0.f,0.f,0.f);
    float4 accB = make_float4(0.f,0.f,0.f,0.f);
    #pragma unroll 2
    for (int k = 0; k < 32; k++) {
        const int   vkA = __shfl_sync(0xffffffffu, viA, k);
        const float wkA = __shfl_sync(0xffffffffu, wA,  k);
        const int   vkB = __shfl_sync(0xffffffffu, viB, k);
        const float wkB = __shfl_sync(0xffffffffu, wB,  k);
        const float4 rA = *(const float4*)(vb + (size_t)vkA * DH + lane*4);
        const float4 rB = *(const float4*)(vb + (size_t)vkB * DH + lane*4);
        accA.x = fmaf(wkA, rA.x, accA.x); accA.y = fmaf(wkA, rA.y, accA.y);
        accA.z = fmaf(wkA, rA.z, accA.z); accA.w = fmaf(wkA, rA.w, accA.w);
        accB.x = fmaf(wkB, rB.x, accB.x); accB.y = fmaf(wkB, rB.y, accB.y);
        accB.z = fmaf(wkB, rB.z, accB.z); accB.w = fmaf(wkB, rB.w, accB.w);
    }
    *(float4*)&g_oh[(size_t)(b*2048 + t)     * 1024 + h*DH + lane*4] = accA;
    *(float4*)&g_oh[(size_t)(b*2048 + t + 1) * 1024 + h*DH + lane*4] = accB;
}

// =================================================================
extern "C" void kernel_launch(void* const* d_in, const int* in_sizes, int n_in,
                              void* d_out, int out_size)
{
    const float* x      = (const float*)d_in[0];
    const float* Wq     = (const float*)d_in[1];
    const float* keys   = (const float*)d_in[2];
    const float* values = (const float*)d_in[3];
    const float* Wo     = (const float*)d_in[4];
    const float* bo     = (const float*)d_in[5];
    float* out = (float*)d_out;

    float* q;  cudaGetSymbolAddress((void**)&q,  g_q);
    float* oh; cudaGetSymbolAddress((void**)&oh, g_oh);

    // 1) q = x @ Wq^T (feeds top-k selection -> split precision, 1 CTA/SM)
    mma_tn<1,1><<<dim3(2048/128, 4096/128), 256>>>(x, Wq, q, nullptr,
                                                   4096, 2048, 1024, 1024, 1024, 2048);
    // 2) dots + stage-1 top-32
    dots_topk_kernel<<<dim3(4096/32, 16), 256>>>(q, keys);
    // 3) combine + softmax + gather (2 slots/warp)
    combine_kernel<<<2048, 256>>>(values);
    // 4) out = oh @ Wo^T + bo (tolerance-checked -> single-pass tf32, 2 CTA/SM)
    mma_tn<0,2><<<dim3(1024/128, 4096/128), 256>>>(oh, Wo, out, bo,
                                                   4096, 1024, 1024, 1024, 1024, 1024);
}

// round 15
// speedup vs baseline: 1.0826x; 1.0260x over previous
#include <cuda_runtime.h>
#include <cuda_bf16.h>

#define NTOK 4096
#define HEADS 8
#define DH 128
#define NKEY 256
#define TOPK 32

static __device__ __forceinline__ float neg_inf() { return __int_as_float(0xff800000); }

// order-preserving float<->uint (total order, no NaNs here)
static __device__ __forceinline__ unsigned ford(float f) {
    unsigned b = __float_as_uint(f);
    return (b & 0x80000000u) ? ~b : (b | 0x80000000u);
}
static __device__ __forceinline__ float forddec(unsigned u) {
    unsigned b = (u & 0x80000000u) ? (u & 0x7fffffffu) : ~u;
    return __uint_as_float(b);
}

// ---------------- scratch (no allocations allowed) ----------------
__device__ float g_q [(size_t)NTOK * 2048];
__device__ float g_s1[(size_t)NTOK * HEADS * 2 * TOPK];
__device__ int   g_i1[(size_t)NTOK * HEADS * 2 * TOPK];
__device__ float g_oh[(size_t)NTOK * 1024];

// =================================================================
// tf32 tensor-core GEMM: C[M,N] = A[M,K] * B[N,K]^T (+ bias[N]).
// Double-buffered smem (1 sync/iter). SPLIT=1: hi/lo 3-mma with B
// pre-split at load. SPLIT=0: single-pass tf32.
// Block 128x128x16, 8 warps, warp tile 32x64, m16n8k8 HMMA.
// =================================================================
static __device__ __forceinline__ void mma1688(float* d, const unsigned* a, const unsigned* b) {
    asm volatile(
        "mma.sync.aligned.m16n8k8.row.col.f32.tf32.tf32.f32 "
        "{%0,%1,%2,%3}, {%4,%5,%6,%7}, {%8,%9}, {%0,%1,%2,%3};"
        : "+f"(d[0]), "+f"(d[1]), "+f"(d[2]), "+f"(d[3])
        : "r"(a[0]), "r"(a[1]), "r"(a[2]), "r"(a[3]), "r"(b[0]), "r"(b[1]));
}
static __device__ __forceinline__ unsigned f2tf32(float f) {
    unsigned r; asm("cvt.rna.tf32.f32 %0, %1;" : "=r"(r) : "f"(f)); return r;
}
static __device__ __forceinline__ void split_tf32(float f, unsigned& hi, unsigned& lo) {
    hi = f2tf32(f);
    lo = f2tf32(f - __uint_as_float(hi));
}

template <int SPLIT, int MINB>
__global__ __launch_bounds__(256, MINB)
void mma_tn(const float* __restrict__ A, const float* __restrict__ B,
            float* __restrict__ C, const float* __restrict__ bias,
            int M, int N, int K, int lda, int ldb, int ldc)
{
    // double-buffered tiles
    __shared__ float    As [2][128][20];
    __shared__ unsigned Bhi[2][128][20];
    __shared__ unsigned Blo[2][128][20];   // used only when SPLIT==1

    const int tid  = threadIdx.x;
    const int lane = tid & 31;
    const int wid  = tid >> 5;
    const int wm   = wid & 3;
    const int wn   = wid >> 2;
    const int m0   = blockIdx.y * 128;
    const int n0   = blockIdx.x * 128;

    const int r0 = tid >> 2;
    const int r1 = r0 + 64;
    const int kc = (tid & 3) << 2;

    const float* Ap0 = A + (size_t)(m0 + r0) * lda + kc;
    const float* Ap1 = A + (size_t)(m0 + r1) * lda + kc;
    const float* Bp0 = B + (size_t)(n0 + r0) * ldb + kc;
    const float* Bp1 = B + (size_t)(n0 + r1) * ldb + kc;

    float4 ra0 = *(const float4*)Ap0;
    float4 ra1 = *(const float4*)Ap1;
    float4 rb0 = *(const float4*)Bp0;
    float4 rb1 = *(const float4*)Bp1;

    float d[2][8][4];
    #pragma unroll
    for (int mt = 0; mt < 2; mt++)
        #pragma unroll
        for (int nt = 0; nt < 8; nt++)
            #pragma unroll
            for (int i = 0; i < 4; i++) d[mt][nt][i] = 0.f;

    const int frow = lane >> 2;
    const int fcol = lane & 3;
    const int nsteps = K >> 4;

    // helper to store a loaded tile into buffer `buf`
    auto store_tile = [&](int buf, const float4& a0, const float4& a1,
                          const float4& b0, const float4& b1) {
        *(float4*)&As[buf][r0][kc] = a0;
        *(float4*)&As[buf][r1][kc] = a1;
        if (SPLIT) {
            unsigned h, l;
            split_tf32(b0.x, h, l); Bhi[buf][r0][kc+0] = h; Blo[buf][r0][kc+0] = l;
            split_tf32(b0.y, h, l); Bhi[buf][r0][kc+1] = h; Blo[buf][r0][kc+1] = l;
            split_tf32(b0.z, h, l); Bhi[buf][r0][kc+2] = h; Blo[buf][r0][kc+2] = l;
            split_tf32(b0.w, h, l); Bhi[buf][r0][kc+3] = h; Blo[buf][r0][kc+3] = l;
            split_tf32(b1.x, h, l); Bhi[buf][r1][kc+0] = h; Blo[buf][r1][kc+0] = l;
            split_tf32(b1.y, h, l); Bhi[buf][r1][kc+1] = h; Blo[buf][r1][kc+1] = l;
            split_tf32(b1.z, h, l); Bhi[buf][r1][kc+2] = h; Blo[buf][r1][kc+2] = l;
            split_tf32(b1.w, h, l); Bhi[buf][r1][kc+3] = h; Blo[buf][r1][kc+3] = l;
        } else {
            Bhi[buf][r0][kc+0] = f2tf32(b0.x); Bhi[buf][r0][kc+1] = f2tf32(b0.y);
            Bhi[buf][r0][kc+2] = f2tf32(b0.z); Bhi[buf][r0][kc+3] = f2tf32(b0.w);
            Bhi[buf][r1][kc+0] = f2tf32(b1.x); Bhi[buf][r1][kc+1] = f2tf32(b1.y);
            Bhi[buf][r1][kc+2] = f2tf32(b1.z); Bhi[buf][r1][kc+3] = f2tf32(b1.w);
        }
    };

    store_tile(0, ra0, ra1, rb0, rb1);
    __syncthreads();

    for (int s = 0; s < nsteps; s++) {
        const int cur = s & 1;
        const int nxt = cur ^ 1;
        if (s + 1 < nsteps) {   // issue global loads early; consumed after compute
            ra0 = *(const float4*)(Ap0 + (s+1)*16);
            ra1 = *(const float4*)(Ap1 + (s+1)*16);
            rb0 = *(const float4*)(Bp0 + (s+1)*16);
            rb1 = *(const float4*)(Bp1 + (s+1)*16);
        }
        #pragma unroll
        for (int k0 = 0; k0 < 16; k0 += 8) {
            unsigned ah[2][4], al[2][4];
            #pragma unroll
            for (int mt = 0; mt < 2; mt++) {
                const int mb = wm*32 + mt*16;
                if (SPLIT) {
                    split_tf32(As[cur][mb + frow    ][k0 + fcol    ], ah[mt][0], al[mt][0]);
                    split_tf32(As[cur][mb + frow + 8][k0 + fcol    ], ah[mt][1], al[mt][1]);
                    split_tf32(As[cur][mb + frow    ][k0 + fcol + 4], ah[mt][2], al[mt][2]);
                    split_tf32(As[cur][mb + frow + 8][k0 + fcol + 4], ah[mt][3], al[mt][3]);
                } else {
                    ah[mt][0] = f2tf32(As[cur][mb + frow    ][k0 + fcol    ]);
                    ah[mt][1] = f2tf32(As[cur][mb + frow + 8][k0 + fcol    ]);
                    ah[mt][2] = f2tf32(As[cur][mb + frow    ][k0 + fcol + 4]);
                    ah[mt][3] = f2tf32(As[cur][mb + frow + 8][k0 + fcol + 4]);
                }
            }
            #pragma unroll
            for (int nt = 0; nt < 8; nt++) {
                const int n = wn*64 + nt*8 + frow;
                unsigned bh[2], bl[2];
                bh[0] = Bhi[cur][n][k0 + fcol    ];
                bh[1] = Bhi[cur][n][k0 + fcol + 4];
                if (SPLIT) {
                    bl[0] = Blo[cur][n][k0 + fcol    ];
                    bl[1] = Blo[cur][n][k0 + fcol + 4];
                    mma1688(d[0][nt], ah[0], bh);
                    mma1688(d[0][nt], ah[0], bl);
                    mma1688(d[0][nt], al[0], bh);
                    mma1688(d[1][nt], ah[1], bh);
                    mma1688(d[1][nt], ah[1], bl);
                    mma1688(d[1][nt], al[1], bh);
                } else {
                    mma1688(d[0][nt], ah[0], bh);
                    mma1688(d[1][nt], ah[1], bh);
                }
            }
        }
        if (s + 1 < nsteps) store_tile(nxt, ra0, ra1, rb0, rb1);
        __syncthreads();
    }

    #pragma unroll
    for (int mt = 0; mt < 2; mt++) {
        const int row = m0 + wm*32 + mt*16 + frow;
        #pragma unroll
        for (int nt = 0; nt < 8; nt++) {
            const int col = n0 + wn*64 + nt*8 + fcol*2;
            float2 bv = make_float2(0.f, 0.f);
            if (bias) bv = *(const float2*)(bias + col);
            float2 o0 = make_float2(d[mt][nt][0] + bv.x, d[mt][nt][1] + bv.y);
            float2 o1 = make_float2(d[mt][nt][2] + bv.x, d[mt][nt][3] + bv.y);
            *(float2*)&C[(size_t)row * ldc + col]       = o0;
            *(float2*)&C[(size_t)(row + 8) * ldc + col] = o1;
        }
    }
}

// =================================================================
// Kernel 2: dots (one (h,p), 32-token tile vs 256 keys) + top-32.
// Extraction: 4 interleaved chains/warp, REDUX + ballot per round.
// =================================================================
__global__ __launch_bounds__(256)
void dots_topk_kernel(const float* __restrict__ qm, const float* __restrict__ keys)
{
    __shared__ float As[8][36];
    __shared__ float Bs[8][264];
    __shared__ float dsm[32*256];

    const int tid  = threadIdx.x;
    const int hp   = blockIdx.y;
    const int h    = hp >> 1;
    const int p    = hp & 1;
    const int t0g  = blockIdx.x * 32;

    const int ty   = tid >> 5;
    const int lane = tid & 31;

    const int at = tid >> 1;
    const int ak = (tid & 1) << 2;
    const float* Ap = qm + (size_t)(t0g + at) * 2048 + p*1024 + h*DH + ak;

    const int bn0 = tid >> 1;
    const int bn1 = bn0 + 128;
    const int bk  = (tid & 1) << 2;
    const float* Kb  = keys + (size_t)h * (NKEY*2*DH) + (size_t)p * DH;
    const float* Bp0 = Kb + (size_t)bn0 * (2*DH) + bk;
    const float* Bp1 = Kb + (size_t)bn1 * (2*DH) + bk;

    float4 ra = make_float4(0.f,0.f,0.f,0.f);
    if (tid < 64) ra = *(const float4*)Ap;
    float4 rb0 = *(const float4*)Bp0;
    float4 rb1 = *(const float4*)Bp1;

    float acc[4][8];
    #pragma unroll
    for (int r = 0; r < 4; r++)
        #pragma unroll
        for (int c = 0; c < 8; c++) acc[r][c] = 0.f;

    for (int s = 0; s < 16; s++) {
        __syncthreads();
        if (tid < 64) {
            As[ak+0][at] = ra.x; As[ak+1][at] = ra.y;
            As[ak+2][at] = ra.z; As[ak+3][at] = ra.w;
        }
        Bs[bk+0][bn0] = rb0.x; Bs[bk+1][bn0] = rb0.y;
        Bs[bk+2][bn0] = rb0.z; Bs[bk+3][bn0] = rb0.w;
        Bs[bk+0][bn1] = rb1.x; Bs[bk+1][bn1] = rb1.y;
        Bs[bk+2][bn1] = rb1.z; Bs[bk+3][bn1] = rb1.w;
        __syncthreads();
        if (s + 1 < 16) {
            if (tid < 64) ra = *(const float4*)(Ap + (s+1)*8);
            rb0 = *(const float4*)(Bp0 + (s+1)*8);
            rb1 = *(const float4*)(Bp1 + (s+1)*8);
        }
        #pragma unroll
        for (int kk = 0; kk < 8; kk++) {
            float4 a4 = *(const float4*)&As[kk][ty*4];
            float4 b0 = *(const float4*)&Bs[kk][lane*4];
            float4 b1 = *(const float4*)&Bs[kk][128 + lane*4];
            float ar[4] = {a4.x,a4.y,a4.z,a4.w};
            float bc[8] = {b0.x,b0.y,b0.z,b0.w,b1.x,b1.y,b1.z,b1.w};
            #pragma unroll
            for (int r = 0; r < 4; r++)
                #pragma unroll
                for (int c = 0; c < 8; c++)
                    acc[r][c] = fmaf(ar[r], bc[c], acc[r][c]);
        }
    }

    #pragma unroll
    for (int r = 0; r < 4; r++) {
        *(float4*)&dsm[(ty*4+r)*256 + lane*4]       = make_float4(acc[r][0],acc[r][1],acc[r][2],acc[r][3]);
        *(float4*)&dsm[(ty*4+r)*256 + 128 + lane*4] = make_float4(acc[r][4],acc[r][5],acc[r][6],acc[r][7]);
    }
    __syncthreads();

    float v[4][8];
    #pragma unroll
    for (int c = 0; c < 4; c++)
        #pragma unroll
        for (int j = 0; j < 8; j++)
            v[c][j] = dsm[(ty*4+c)*256 + j*32 + lane];

    unsigned taken[4] = {0u,0u,0u,0u};
    float outv[4] = {0.f,0.f,0.f,0.f};
    int   outn[4] = {0,0,0,0};

    #pragma unroll 1
    for (int kk = 0; kk < 32; kk++) {
        unsigned u[4]; int ln[4];
        #pragma unroll
        for (int c = 0; c < 4; c++) {
            float lv = neg_inf(); int l = 0x7fffffff;
            #pragma unroll
            for (int j = 0; j < 8; j++) {
                float cand = ((taken[c] >> j) & 1u) ? neg_inf() : v[c][j];
                if (cand > lv) { lv = cand; l = j*32 + lane; }
            }
            u[c] = ford(lv); ln[c] = l;
        }
        unsigned umax[4];
        #pragma unroll
        for (int c = 0; c < 4; c++) umax[c] = __reduce_max_sync(0xffffffffu, u[c]);
        unsigned ball[4];
        #pragma unroll
        for (int c = 0; c < 4; c++) ball[c] = __ballot_sync(0xffffffffu, u[c] == umax[c]);
        #pragma unroll
        for (int c = 0; c < 4; c++) {
            const int wl = __ffs(ball[c]) - 1;
            const int wn = __shfl_sync(0xffffffffu, ln[c], wl);
            if (kk == lane) { outv[c] = forddec(umax[c]); outn[c] = wn; }
            if (wl == lane) taken[c] |= 1u << (ln[c] >> 5);
        }
    }

    #pragma unroll
    for (int c = 0; c < 4; c++) {
        const size_t base = ((((size_t)(t0g + ty*4 + c)) * HEADS + h) * 2 + p) * TOPK;
        g_s1[base + lane] = outv[c];
        g_i1[base + lane] = outn[c];
    }
}

// =================================================================
// Kernel 3: combine, 2 slots/warp, software-pipelined gather
// (8 indices prefetched -> 16 LDG.128 in flight).
// =================================================================
__global__ __launch_bounds__(256)
void combine_kernel(const float* __restrict__ values)
{
    const int warp  = threadIdx.x >> 5;
    const int lane  = threadIdx.x & 31;
    const int slotA = blockIdx.x * 16 + warp * 2;
    const int t  = slotA & 2047;
    const int h  = (slotA >> 11) & 7;
    const int b  = slotA >> 14;
    const int u  = t >> 1;

    const size_t b0A = ((((size_t)(b*2048 + u))        * HEADS + h) * 2 + 0) * TOPK;
    const size_t b1A = ((((size_t)(b*2048 + u + 1024)) * HEADS + h) * 2 + 0) * TOPK;
    const size_t b0B = b0A + TOPK;
    const size_t b1B = b1A + TOPK;

    const float s0A = g_s1[b0A + lane]; const int i0A = g_i1[b0A + lane];
    const float s1A = g_s1[b1A + lane]; const int i1A = g_i1[b1A + lane];
    const float s0B = g_s1[b0B + lane]; const int i0B = g_i1[b0B + lane];
    const float s1B = g_s1[b1B + lane]; const int i1B = g_i1[b1B + lane];

    int ptrA = 0, ptrB = 0;
    float rvA = 0.f, rvB = 0.f; int rfA = 0, rfB = 0;
    #pragma unroll 1
    for (int it = 0; it < 32; it++) {
        const int ppA = ptrA < 32 ? ptrA : 31;
        const int ppB = ptrB < 32 ? ptrB : 31;
        float cvA = __shfl_sync(0xffffffffu, s0A, ppA) + s1A;
        float cvB = __shfl_sync(0xffffffffu, s0B, ppB) + s1B;
        int flA = ptrA * 32 + lane;
        int flB = ptrB * 32 + lane;
        if (ptrA >= 32) { cvA = neg_inf(); flA = 0x7fffffff; }
        if (ptrB >= 32) { cvB = neg_inf(); flB = 0x7fffffff; }
        const unsigned uA = ford(cvA), uB = ford(cvB);
        const unsigned umA = __reduce_max_sync(0xffffffffu, uA);
        const unsigned umB = __reduce_max_sync(0xffffffffu, uB);
        const unsigned baA = __ballot_sync(0xffffffffu, uA == umA);
        const unsigned baB = __ballot_sync(0xffffffffu, uB == umB);
        const int wlA = __ffs(baA) - 1;
        const int wlB = __ffs(baB) - 1;
        const int wfA = __shfl_sync(0xffffffffu, flA, wlA);
        const int wfB = __shfl_sync(0xffffffffu, flB, wlB);
        if (it == lane) { rvA = forddec(umA); rfA = wfA;
                          rvB = forddec(umB); rfB = wfB; }
        if (wlA == lane && flA != 0x7fffffff) ptrA++;
        if (wlB == lane && flB != 0x7fffffff) ptrB++;
    }

    const float mxA = __shfl_sync(0xffffffffu, rvA, 0);
    const float mxB = __shfl_sync(0xffffffffu, rvB, 0);
    float eA = __expf(rvA - mxA);
    float eB = __expf(rvB - mxB);
    float sA = eA, sB = eB;
    #pragma unroll
    for (int o = 16; o > 0; o >>= 1) {
        sA += __shfl_xor_sync(0xffffffffu, sA, o);
        sB += __shfl_xor_sync(0xffffffffu, sB, o);
    }
    const float wA = eA / sA;
    const float wB = eB / sB;

    const int viA = __shfl_sync(0xffffffffu, i0A, rfA >> 5) * NKEY
                  + __shfl_sync(0xffffffffu, i1A, rfA & 31);
    const int viB = __shfl_sync(0xffffffffu, i0B, rfB >> 5) * NKEY
                  + __shfl_sync(0xffffffffu, i1B, rfB & 31);

    const float* vb = values + (size_t)h * ((size_t)NKEY*NKEY) * DH;
    float4 accA = make_float4(0.f,0.f,0.f,0.f);
    float4 accB = make_float4(0.f,0.f,0.f,0.f);

    #pragma unroll 1
    for (int k0 = 0; k0 < 32; k0 += 8) {
        int   iA[8], iB[8];
        float fA[8], fB[8];
        #pragma unroll
        for (int j = 0; j < 8; j++) {
            iA[j] = __shfl_sync(0xffffffffu, viA, k0 + j);
            fA[j] = __shfl_sync(0xffffffffu, wA,  k0 + j);
            iB[j] = __shfl_sync(0xffffffffu, viB, k0 + j);
            fB[j] = __shfl_sync(0xffffffffu, wB,  k0 + j);
        }
        float4 rA[8], rB[8];
        #pragma unroll
        for (int j = 0; j < 8; j++) {
            rA[j] = *(const float4*)(vb + (size_t)iA[j] * DH + lane*4);
            rB[j] = *(const float4*)(vb + (size_t)iB[j] * DH + lane*4);
        }
        #pragma unroll
        for (int j = 0; j < 8; j++) {
            accA.x = fmaf(fA[j], rA[j].x, accA.x);
            accA.y = fmaf(fA[j], rA[j].y, accA.y);
            accA.z = fmaf(fA[j], rA[j].z, accA.z);
            accA.w = fmaf(fA[j], rA[j].w, accA.w);
            accB.x = fmaf(fB[j], rB[j].x, accB.x);
            accB.y = fmaf(fB[j], rB[j].y, accB.y);
            accB.z = fmaf(fB[j], rB[j].z, accB.z);
            accB.w = fmaf(fB[j], rB[j].w, accB.w);
        }
    }

    *(float4*)&g_oh[(size_t)(b*2048 + t)     * 1024 + h*DH + lane*4] = accA;
    *(float4*)&g_oh[(size_t)(b*2048 + t + 1) * 1024 + h*DH + lane*4] = accB;
}

// =================================================================
extern "C" void kernel_launch(void* const* d_in, const int* in_sizes, int n_in,
                              void* d_out, int out_size)
{
    const float* x      = (const float*)d_in[0];
    const float* Wq     = (const float*)d_in[1];
    const float* keys   = (const float*)d_in[2];
    const float* values = (const float*)d_in[3];
    const float* Wo     = (const float*)d_in[4];
    const float* bo     = (const float*)d_in[5];
    float* out = (float*)d_out;

    float* q;  cudaGetSymbolAddress((void**)&q,  g_q);
    float* oh; cudaGetSymbolAddress((void**)&oh, g_oh);

    // 1) q = x @ Wq^T (selection path -> split precision)
    mma_tn<1,1><<<dim3(2048/128, 4096/128), 256>>>(x, Wq, q, nullptr,
                                                   4096, 2048, 1024, 1024, 1024, 2048);
    // 2) dots + stage-1 top-32
    dots_topk_kernel<<<dim3(4096/32, 16), 256>>>(q, keys);
    // 3) combine + softmax + gather
    combine_kernel<<<2048, 256>>>(values);
    // 4) out = oh @ Wo^T + bo (tolerance-checked -> single-pass tf32)
    mma_tn<0,2><<<dim3(1024/128, 4096/128), 256>>>(oh, Wo, out, bo,
                                                   4096, 1024, 1024, 1024, 1024, 1024);
}